// round 6
// baseline (speedup 1.0000x reference)
#include <cuda_runtime.h>
#include <cuda_bf16.h>
#include <math.h>
#include <stdint.h>

#define LSEQ   4096
#define HIDDEN 4096
#define NH     32
#define NKV    8
#define HD     128
#define CHUNKS 128
#define NC     32
#define QDIM   4096   // NH*HD
#define KVDIM  1024   // NKV*HD
#define NELEM_BIG ((size_t)LSEQ * HIDDEN)     // 16M
#define NELEM_KV  ((size_t)KVDIM * HIDDEN)    // 4M

// single dynamic smem declaration for ALL kernels
extern __shared__ __align__(1024) unsigned char dyn_smem[];

// ---------------- scratch (static device globals; no allocation) ----------------
__device__ float g_q[(size_t)LSEQ * QDIM];
__device__ float g_k[(size_t)LSEQ * KVDIM];
__device__ float g_v[(size_t)LSEQ * KVDIM];
__device__ float g_gate[(size_t)LSEQ * QDIM];
__device__ float g_y[(size_t)LSEQ * QDIM];
__device__ float g_dt[LSEQ * NH];
__device__ float g_G[LSEQ * NH];
__device__ float g_cdec[NC * NH];
__device__ float g_cs[(size_t)NC * NH * HD * HD];
__device__ float g_prev[(size_t)NC * NH * HD * HD];

// bf16 hi/lo split buffers
__device__ __nv_bfloat16 g_hsh[NELEM_BIG], g_hsl[NELEM_BIG];
__device__ __nv_bfloat16 g_wqh[NELEM_BIG], g_wql[NELEM_BIG];
__device__ __nv_bfloat16 g_wgh[NELEM_BIG], g_wgl[NELEM_BIG];
__device__ __nv_bfloat16 g_woh[NELEM_BIG], g_wol[NELEM_BIG];
__device__ __nv_bfloat16 g_wkh[NELEM_KV],  g_wkl[NELEM_KV];
__device__ __nv_bfloat16 g_wvh[NELEM_KV],  g_wvl[NELEM_KV];
__device__ __nv_bfloat16 g_yh[NELEM_BIG],  g_yl[NELEM_BIG];

// ---------------- helpers ----------------
__device__ __forceinline__ uint32_t smem_u32(const void* p) {
    uint32_t a;
    asm("{ .reg .u64 t; cvta.to.shared.u64 t, %1; cvt.u32.u64 %0, t; }" : "=r"(a) : "l"(p));
    return a;
}
__device__ __forceinline__ void cp_async16(uint32_t s, const void* g) {
    asm volatile("cp.async.cg.shared.global [%0], [%1], 16;" :: "r"(s), "l"(g));
}
#define CP_COMMIT() asm volatile("cp.async.commit_group;" ::: "memory")
#define CP_WAIT1()  asm volatile("cp.async.wait_group 1;" ::: "memory")

__device__ __forceinline__ void ldsm_x4(uint32_t* r, uint32_t addr) {
    asm volatile("ldmatrix.sync.aligned.m8n8.x4.shared.b16 {%0,%1,%2,%3}, [%4];"
                 : "=r"(r[0]), "=r"(r[1]), "=r"(r[2]), "=r"(r[3]) : "r"(addr));
}
__device__ __forceinline__ void mma_bf16(float* c, const uint32_t* a, const uint32_t* b) {
    asm volatile("mma.sync.aligned.m16n8k16.row.col.f32.bf16.bf16.f32 "
                 "{%0,%1,%2,%3}, {%4,%5,%6,%7}, {%8,%9}, {%0,%1,%2,%3};"
                 : "+f"(c[0]), "+f"(c[1]), "+f"(c[2]), "+f"(c[3])
                 : "r"(a[0]), "r"(a[1]), "r"(a[2]), "r"(a[3]), "r"(b[0]), "r"(b[1]));
}

// ---------------- fp32 -> bf16 hi/lo split ----------------
__global__ void conv_split(const float* __restrict__ src, __nv_bfloat16* __restrict__ hi,
                           __nv_bfloat16* __restrict__ lo, int n4) {
    int i = blockIdx.x * blockDim.x + threadIdx.x;
    if (i >= n4) return;
    float4 v = ((const float4*)src)[i];
    __nv_bfloat162 h01 = __floats2bfloat162_rn(v.x, v.y);
    __nv_bfloat162 h23 = __floats2bfloat162_rn(v.z, v.w);
    float2 f01 = __bfloat1622float2(h01);
    float2 f23 = __bfloat1622float2(h23);
    __nv_bfloat162 l01 = __floats2bfloat162_rn(v.x - f01.x, v.y - f01.y);
    __nv_bfloat162 l23 = __floats2bfloat162_rn(v.z - f23.x, v.w - f23.y);
    ((__nv_bfloat162*)hi)[2 * i]     = h01;
    ((__nv_bfloat162*)hi)[2 * i + 1] = h23;
    ((__nv_bfloat162*)lo)[2 * i]     = l01;
    ((__nv_bfloat162*)lo)[2 * i + 1] = l23;
}

// ---------------- bf16x3 mma GEMM, cp.async 3-stage + ldmatrix ----------------
// C[M,N] = (Ah+Al)[M,K] @ (Bh+Bl)[N,K]^T.  CTA 128x128, BK=32, 256 thr (8 warps 2x4).
// smem stage (32KB): Ah@0, Al@8K, Bh@16K, Bl@24K. Tile [128 rows][32 k] bf16, row=64B,
// 16B chunk swizzle: ch ^ ((row>>1)&3). K%32==0, M,N%128==0.
__global__ void __launch_bounds__(256, 1) gemm_mma(const __nv_bfloat16* __restrict__ Ah,
                                                   const __nv_bfloat16* __restrict__ Al,
                                                   const __nv_bfloat16* __restrict__ Bh,
                                                   const __nv_bfloat16* __restrict__ Bl,
                                                   float* __restrict__ C,
                                                   int M, int N, int K) {
    unsigned char* smem = dyn_smem;     // 3 stages x 32KB
    const uint32_t smem_b = smem_u32(smem);
    const int tid = threadIdx.x;
    const int warp = tid >> 5, lane = tid & 31;
    const int wm = warp >> 2, wn = warp & 3;     // 2 x 4 warps, warp tile 64x32
    const int bm = blockIdx.y * 128, bn = blockIdx.x * 128;

    float acc[4][4][4];
#pragma unroll
    for (int a = 0; a < 4; a++)
#pragma unroll
        for (int b = 0; b < 4; b++)
#pragma unroll
            for (int c = 0; c < 4; c++) acc[a][b][c] = 0.f;

    // loader assignment: 4 tiles x 64 threads; each thread: 2 rows x 4 chunks
    const int t4 = tid >> 6;
    const int j = tid & 63;
    const __nv_bfloat16* src = (t4 == 0) ? Ah : (t4 == 1) ? Al : (t4 == 2) ? Bh : Bl;
    const int baserow = (t4 < 2) ? bm : bn;
    const uint32_t tilebase = (uint32_t)t4 * 8192u;

    auto issue_stage = [&](int kb) {
        const int stage = kb % 3;
        const int kc = kb * 32;
        const uint32_t sb = smem_b + (uint32_t)stage * 32768u + tilebase;
#pragma unroll
        for (int rr = 0; rr < 2; rr++) {
            const int row = 2 * j + rr;
            const __nv_bfloat16* gr = src + (size_t)(baserow + row) * K + kc;
            const uint32_t sw = ((uint32_t)row >> 1) & 3u;
            const uint32_t rbase = sb + (uint32_t)row * 64u;
#pragma unroll
            for (int ch = 0; ch < 4; ch++) {
                cp_async16(rbase + ((ch ^ sw) * 16u), gr + ch * 8);
            }
        }
    };

    const int nk = K >> 5;
    issue_stage(0); CP_COMMIT();
    issue_stage(1); CP_COMMIT();

    for (int kb = 0; kb < nk; kb++) {
        CP_WAIT1();
        __syncthreads();
        if (kb + 2 < nk) issue_stage(kb + 2);
        CP_COMMIT();

        const uint32_t sb = smem_b + (uint32_t)(kb % 3) * 32768u;
        const uint32_t sAh = sb, sAl = sb + 8192u, sBh = sb + 16384u, sBl = sb + 24576u;

#pragma unroll
        for (int ks = 0; ks < 2; ks++) {
            // A fragment addresses (per mt): lane -> (row, chunk)
            uint32_t ah[4][4], al[4][4], bh[2][4], bl[2][4];
#pragma unroll
            for (int mt = 0; mt < 4; mt++) {
                const int row = wm * 64 + mt * 16 + (lane & 7) + ((lane & 8) ? 8 : 0);
                const int ch = 2 * ks + ((lane & 16) ? 1 : 0);
                const uint32_t off = (uint32_t)row * 64u + (uint32_t)((ch ^ ((row >> 1) & 3)) * 16);
                ldsm_x4(ah[mt], sAh + off);
                ldsm_x4(al[mt], sAl + off);
            }
#pragma unroll
            for (int p = 0; p < 2; p++) {
                const int row = wn * 32 + p * 16 + (lane & 7) + ((lane & 16) ? 8 : 0);
                const int ch = 2 * ks + ((lane & 8) ? 1 : 0);
                const uint32_t off = (uint32_t)row * 64u + (uint32_t)((ch ^ ((row >> 1) & 3)) * 16);
                ldsm_x4(bh[p], sBh + off);
                ldsm_x4(bl[p], sBl + off);
            }
#pragma unroll
            for (int mt = 0; mt < 4; mt++) {
#pragma unroll
                for (int nt = 0; nt < 4; nt++) {
                    const uint32_t* bhf = &bh[nt >> 1][(nt & 1) * 2];
                    const uint32_t* blf = &bl[nt >> 1][(nt & 1) * 2];
                    mma_bf16(acc[mt][nt], ah[mt], bhf);   // hh
                    mma_bf16(acc[mt][nt], ah[mt], blf);   // hl
                    mma_bf16(acc[mt][nt], al[mt], bhf);   // lh
                }
            }
        }
    }

    // epilogue
#pragma unroll
    for (int mt = 0; mt < 4; mt++) {
        const int row0 = bm + wm * 64 + mt * 16 + (lane >> 2);
#pragma unroll
        for (int nt = 0; nt < 4; nt++) {
            const int col = bn + wn * 32 + nt * 8 + (lane & 3) * 2;
            *(float2*)(C + (size_t)row0 * N + col) = make_float2(acc[mt][nt][0], acc[mt][nt][1]);
            *(float2*)(C + (size_t)(row0 + 8) * N + col) = make_float2(acc[mt][nt][2], acc[mt][nt][3]);
        }
    }
}

// ---------------- dt = softplus(hs @ Win^T + dt_bias) ----------------
__global__ void dt_kernel(const float* __restrict__ hs, const float* __restrict__ Win,
                          const float* __restrict__ dtb) {
    __shared__ float srow[HIDDEN];
    __shared__ float red[256];
    const int l = blockIdx.x;
    for (int k = threadIdx.x; k < HIDDEN; k += 256) srow[k] = hs[(size_t)l * HIDDEN + k];
    __syncthreads();
    const int h = threadIdx.x & 31;
    const int part = threadIdx.x >> 5;
    const float* w = Win + (size_t)h * HIDDEN + part * 512;
    const float* s = srow + part * 512;
    float acc = 0.f;
#pragma unroll 4
    for (int k = 0; k < 512; k++) acc += s[k] * w[k];
    red[threadIdx.x] = acc;
    __syncthreads();
    if (threadIdx.x < 32) {
        float t = 0.f;
#pragma unroll
        for (int p = 0; p < 8; p++) t += red[p * 32 + h];
        t += dtb[h];
        float sp = fmaxf(t, 0.f) + log1pf(expf(-fabsf(t)));
        g_dt[l * NH + h] = sp;
    }
}

// ---------------- per-(chunk,head) inclusive cumsum of g = dt*A ----------------
__global__ void scan_kernel(const float* __restrict__ A_log) {
    const int hc = blockIdx.x;
    const int h = hc & (NH - 1);
    const int c = hc >> 5;
    const float A = -expf(A_log[h]);
    const int lane = threadIdx.x;
    float carry = 0.f;
    for (int s0 = 0; s0 < CHUNKS; s0 += 32) {
        const int l = c * CHUNKS + s0 + lane;
        float val = g_dt[l * NH + h] * A;
#pragma unroll
        for (int off = 1; off < 32; off <<= 1) {
            float n = __shfl_up_sync(0xffffffffu, val, off);
            if (lane >= off) val += n;
        }
        val += carry;
        g_G[l * NH + h] = val;
        carry = __shfl_sync(0xffffffffu, val, 31);
    }
    if (lane == 31) g_cdec[c * NH + h] = expf(carry);
}

// ---------------- RoPE in place ----------------
__global__ void rope_kernel(float* __restrict__ x, int nheads) {
    const long idx = (long)blockIdx.x * blockDim.x + threadIdx.x;
    const long total = (long)LSEQ * nheads * 64;
    if (idx >= total) return;
    const int d = (int)(idx & 63);
    const int h = (int)((idx >> 6) % nheads);
    const long l = idx / ((long)64 * nheads);
    const float inv = powf(10000.0f, -(2.0f * d) / 128.0f);
    const float ang = (float)l * inv;
    float cs, sn;
    __sincosf(ang, &sn, &cs);
    float* base = x + l * (size_t)(nheads * HD) + (size_t)h * HD;
    const float x1 = base[d];
    const float x2 = base[d + 64];
    base[d]      = x1 * cs - x2 * sn;
    base[d + 64] = x2 * cs + x1 * sn;
}

// ---------------- intra-chunk: scores, decay mask, y_intra, cstates ----------------
__global__ void intra_kernel() {
    float* smem = (float*)dyn_smem;
    float* sP = smem;                 // 128*129, P^T (stored [j][i])
    float* sA = sP + 128 * 129;       // 16*128
    float* sB = sA + 16 * 128;        // 16*128
    __shared__ float sG[128];
    __shared__ float sDt[128];

    const int c = blockIdx.x, h = blockIdx.y;
    const int kvh = h >> 2;
    const int tid = threadIdx.x;
    const int tr = tid >> 4, tc = tid & 15;
    const float* qp = g_q + (size_t)(c * CHUNKS) * QDIM + (size_t)h * HD;
    const float* kp = g_k + (size_t)(c * CHUNKS) * KVDIM + (size_t)kvh * HD;
    const float* vp = g_v + (size_t)(c * CHUNKS) * KVDIM + (size_t)kvh * HD;

    if (tid < 128) {
        sG[tid] = g_G[(c * CHUNKS + tid) * NH + h];
        sDt[tid] = g_dt[(c * CHUNKS + tid) * NH + h];
    }
    __syncthreads();
    const float Glast = sG[127];

    float acc[8][8];
#pragma unroll
    for (int i = 0; i < 8; i++)
#pragma unroll
        for (int j = 0; j < 8; j++) acc[i][j] = 0.f;

    const int rowA = tid >> 1;
    const int kk0 = (tid & 1) * 8;
    for (int d0 = 0; d0 < HD; d0 += 16) {
        const float* ap = qp + (size_t)rowA * QDIM + d0 + kk0;
        float4 a0 = *(const float4*)ap;
        float4 a1 = *(const float4*)(ap + 4);
        sA[(kk0 + 0) * 128 + rowA] = a0.x;
        sA[(kk0 + 1) * 128 + rowA] = a0.y;
        sA[(kk0 + 2) * 128 + rowA] = a0.z;
        sA[(kk0 + 3) * 128 + rowA] = a0.w;
        sA[(kk0 + 4) * 128 + rowA] = a1.x;
        sA[(kk0 + 5) * 128 + rowA] = a1.y;
        sA[(kk0 + 6) * 128 + rowA] = a1.z;
        sA[(kk0 + 7) * 128 + rowA] = a1.w;
        const float* bp = kp + (size_t)rowA * KVDIM + d0 + kk0;
        float4 b0 = *(const float4*)bp;
        float4 b1 = *(const float4*)(bp + 4);
        sB[(kk0 + 0) * 128 + rowA] = b0.x;
        sB[(kk0 + 1) * 128 + rowA] = b0.y;
        sB[(kk0 + 2) * 128 + rowA] = b0.z;
        sB[(kk0 + 3) * 128 + rowA] = b0.w;
        sB[(kk0 + 4) * 128 + rowA] = b1.x;
        sB[(kk0 + 5) * 128 + rowA] = b1.y;
        sB[(kk0 + 6) * 128 + rowA] = b1.z;
        sB[(kk0 + 7) * 128 + rowA] = b1.w;
        __syncthreads();
#pragma unroll
        for (int kk = 0; kk < 16; kk++) {
            float av[8], bv[8];
#pragma unroll
            for (int i = 0; i < 8; i++) av[i] = sA[kk * 128 + tr * 8 + i];
#pragma unroll
            for (int j = 0; j < 8; j++) bv[j] = sB[kk * 128 + tc * 8 + j];
#pragma unroll
            for (int i = 0; i < 8; i++)
#pragma unroll
                for (int j = 0; j < 8; j++) acc[i][j] += av[i] * bv[j];
        }
        __syncthreads();
    }

#pragma unroll
    for (int ii = 0; ii < 8; ii++) {
        const int i = tr * 8 + ii;
        const float Gi = sG[i];
#pragma unroll
        for (int jj = 0; jj < 8; jj++) {
            const int j = tc * 8 + jj;
            const float p = (i >= j) ? acc[ii][jj] * expf(Gi - sG[j]) : 0.f;
            sP[j * 129 + i] = p;
        }
    }
    __syncthreads();

#pragma unroll
    for (int i = 0; i < 8; i++)
#pragma unroll
        for (int j = 0; j < 8; j++) acc[i][j] = 0.f;
    {
        const int kkl = tid >> 4;
        const int e0 = (tid & 15) * 8;
        for (int j0 = 0; j0 < 128; j0 += 16) {
            const float dtv = sDt[j0 + kkl];
            const float* xp = vp + (size_t)(j0 + kkl) * KVDIM + e0;
            float4 x0 = *(const float4*)xp;
            float4 x1 = *(const float4*)(xp + 4);
            sB[kkl * 128 + e0 + 0] = x0.x * dtv;
            sB[kkl * 128 + e0 + 1] = x0.y * dtv;
            sB[kkl * 128 + e0 + 2] = x0.z * dtv;
            sB[kkl * 128 + e0 + 3] = x0.w * dtv;
            sB[kkl * 128 + e0 + 4] = x1.x * dtv;
            sB[kkl * 128 + e0 + 5] = x1.y * dtv;
            sB[kkl * 128 + e0 + 6] = x1.z * dtv;
            sB[kkl * 128 + e0 + 7] = x1.w * dtv;
            __syncthreads();
#pragma unroll
            for (int kk = 0; kk < 16; kk++) {
                float av[8], bv[8];
#pragma unroll
                for (int i = 0; i < 8; i++) av[i] = sP[(j0 + kk) * 129 + tr * 8 + i];
#pragma unroll
                for (int j = 0; j < 8; j++) bv[j] = sB[kk * 128 + tc * 8 + j];
#pragma unroll
                for (int i = 0; i < 8; i++)
#pragma unroll
                    for (int j = 0; j < 8; j++) acc[i][j] += av[i] * bv[j];
            }
            __syncthreads();
        }
    }
#pragma unroll
    for (int ii = 0; ii < 8; ii++) {
        float* yp = g_y + (size_t)(c * CHUNKS + tr * 8 + ii) * QDIM + (size_t)h * HD + tc * 8;
        *(float4*)yp = make_float4(acc[ii][0], acc[ii][1], acc[ii][2], acc[ii][3]);
        *(float4*)(yp + 4) = make_float4(acc[ii][4], acc[ii][5], acc[ii][6], acc[ii][7]);
    }

#pragma unroll
    for (int i = 0; i < 8; i++)
#pragma unroll
        for (int j = 0; j < 8; j++) acc[i][j] = 0.f;
    {
        const int kkl = tid >> 4;
        const int e0 = (tid & 15) * 8;
        for (int j0 = 0; j0 < 128; j0 += 16) {
            const float w = expf(Glast - sG[j0 + kkl]);
            const float dtv = sDt[j0 + kkl];
            const float* kp2 = kp + (size_t)(j0 + kkl) * KVDIM + e0;
            const float* xp = vp + (size_t)(j0 + kkl) * KVDIM + e0;
            float4 k0v = *(const float4*)kp2;
            float4 k1v = *(const float4*)(kp2 + 4);
            float4 x0 = *(const float4*)xp;
            float4 x1 = *(const float4*)(xp + 4);
            sA[kkl * 128 + e0 + 0] = k0v.x * w;
            sA[kkl * 128 + e0 + 1] = k0v.y * w;
            sA[kkl * 128 + e0 + 2] = k0v.z * w;
            sA[kkl * 128 + e0 + 3] = k0v.w * w;
            sA[kkl * 128 + e0 + 4] = k1v.x * w;
            sA[kkl * 128 + e0 + 5] = k1v.y * w;
            sA[kkl * 128 + e0 + 6] = k1v.z * w;
            sA[kkl * 128 + e0 + 7] = k1v.w * w;
            sB[kkl * 128 + e0 + 0] = x0.x * dtv;
            sB[kkl * 128 + e0 + 1] = x0.y * dtv;
            sB[kkl * 128 + e0 + 2] = x0.z * dtv;
            sB[kkl * 128 + e0 + 3] = x0.w * dtv;
            sB[kkl * 128 + e0 + 4] = x1.x * dtv;
            sB[kkl * 128 + e0 + 5] = x1.y * dtv;
            sB[kkl * 128 + e0 + 6] = x1.z * dtv;
            sB[kkl * 128 + e0 + 7] = x1.w * dtv;
            __syncthreads();
#pragma unroll
            for (int kk = 0; kk < 16; kk++) {
                float av[8], bv[8];
#pragma unroll
                for (int i = 0; i < 8; i++) av[i] = sA[kk * 128 + tr * 8 + i];
#pragma unroll
                for (int j = 0; j < 8; j++) bv[j] = sB[kk * 128 + tc * 8 + j];
#pragma unroll
                for (int i = 0; i < 8; i++)
#pragma unroll
                    for (int j = 0; j < 8; j++) acc[i][j] += av[i] * bv[j];
            }
            __syncthreads();
        }
    }
    float* csp = g_cs + (size_t)(c * NH + h) * HD * HD;
#pragma unroll
    for (int ii = 0; ii < 8; ii++) {
        float* cp = csp + (size_t)(tr * 8 + ii) * HD + tc * 8;
        *(float4*)cp = make_float4(acc[ii][0], acc[ii][1], acc[ii][2], acc[ii][3]);
        *(float4*)(cp + 4) = make_float4(acc[ii][4], acc[ii][5], acc[ii][6], acc[ii][7]);
    }
}

// ---------------- sequential chunk recurrence ----------------
__global__ void recur_kernel() {
    const int idx = blockIdx.x * blockDim.x + threadIdx.x;
    if (idx >= NH * HD * HD) return;
    const int h = idx / (HD * HD);
    const int de = idx % (HD * HD);
    float state = 0.f;
#pragma unroll 1
    for (int c = 0; c < NC; c++) {
        const size_t off = (size_t)(c * NH + h) * HD * HD + de;
        g_prev[off] = state;
        state = state * g_cdec[c * NH + h] + g_cs[off];
    }
}

// ---------------- inter-chunk + combine + RMSNorm + SiLU gate ----------------
__global__ void inter_kernel(const float* __restrict__ gnorm) {
    float* smem = (float*)dyn_smem;
    float* sY = smem;               // 128*129
    float* sA = sY + 128 * 129;     // 16*128
    float* sB = sA + 16 * 128;      // 16*128
    __shared__ float sG[128];
    __shared__ float sScale[128];
    __shared__ float sGn[128];

    const int c = blockIdx.x, h = blockIdx.y;
    const int tid = threadIdx.x;
    const int tr = tid >> 4, tc = tid & 15;
    const float* qp = g_q + (size_t)(c * CHUNKS) * QDIM + (size_t)h * HD;
    const float* pp = g_prev + (size_t)(c * NH + h) * HD * HD;

    if (tid < 128) {
        sG[tid] = g_G[(c * CHUNKS + tid) * NH + h];
        sGn[tid] = gnorm[tid];
    }
    __syncthreads();

    float acc[8][8];
#pragma unroll
    for (int i = 0; i < 8; i++)
#pragma unroll
        for (int j = 0; j < 8; j++) acc[i][j] = 0.f;

    const int rowA = tid >> 1;
    const int kk0 = (tid & 1) * 8;
    const int kkl = tid >> 4;
    const int e0 = (tid & 15) * 8;
    for (int d0 = 0; d0 < HD; d0 += 16) {
        const float eg = expf(sG[rowA]);
        const float* ap = qp + (size_t)rowA * QDIM + d0 + kk0;
        float4 a0 = *(const float4*)ap;
        float4 a1 = *(const float4*)(ap + 4);
        sA[(kk0 + 0) * 128 + rowA] = a0.x * eg;
        sA[(kk0 + 1) * 128 + rowA] = a0.y * eg;
        sA[(kk0 + 2) * 128 + rowA] = a0.z * eg;
        sA[(kk0 + 3) * 128 + rowA] = a0.w * eg;
        sA[(kk0 + 4) * 128 + rowA] = a1.x * eg;
        sA[(kk0 + 5) * 128 + rowA] = a1.y * eg;
        sA[(kk0 + 6) * 128 + rowA] = a1.z * eg;
        sA[(kk0 + 7) * 128 + rowA] = a1.w * eg;
        const float* bp = pp + (size_t)(d0 + kkl) * HD + e0;
        float4 b0 = *(const float4*)bp;
        float4 b1 = *(const float4*)(bp + 4);
        sB[kkl * 128 + e0 + 0] = b0.x;
        sB[kkl * 128 + e0 + 1] = b0.y;
        sB[kkl * 128 + e0 + 2] = b0.z;
        sB[kkl * 128 + e0 + 3] = b0.w;
        sB[kkl * 128 + e0 + 4] = b1.x;
        sB[kkl * 128 + e0 + 5] = b1.y;
        sB[kkl * 128 + e0 + 6] = b1.z;
        sB[kkl * 128 + e0 + 7] = b1.w;
        __syncthreads();
#pragma unroll
        for (int kk = 0; kk < 16; kk++) {
            float av[8], bv[8];
#pragma unroll
            for (int i = 0; i < 8; i++) av[i] = sA[kk * 128 + tr * 8 + i];
#pragma unroll
            for (int j = 0; j < 8; j++) bv[j] = sB[kk * 128 + tc * 8 + j];
#pragma unroll
            for (int i = 0; i < 8; i++)
#pragma unroll
                for (int j = 0; j < 8; j++) acc[i][j] += av[i] * bv[j];
        }
        __syncthreads();
    }

#pragma unroll
    for (int ii = 0; ii < 8; ii++) {
        const int i = tr * 8 + ii;
        const float* yin = g_y + (size_t)(c * CHUNKS + i) * QDIM + (size_t)h * HD + tc * 8;
#pragma unroll
        for (int jj = 0; jj < 8; jj++) {
            sY[i * 129 + tc * 8 + jj] = acc[ii][jj] + yin[jj];
        }
    }
    __syncthreads();

    if (tid < 128) {
        float s = 0.f;
#pragma unroll 4
        for (int e = 0; e < 128; e++) {
            float t = sY[tid * 129 + e];
            s += t * t;
        }
        sScale[tid] = rsqrtf(s * (1.0f / 128.0f) + 1e-5f);
    }
    __syncthreads();

    for (int idx = tid; idx < 128 * 128; idx += 256) {
        const int i = idx >> 7, e = idx & 127;
        const size_t off = (size_t)(c * CHUNKS + i) * QDIM + (size_t)h * HD + e;
        const float gv = g_gate[off];
        const float sig = 1.f / (1.f + expf(-gv));
        g_y[off] = sY[i * 129 + e] * sScale[i] * sGn[e] * gv * sig;
    }
}

// ---------------- launch ----------------
extern "C" void kernel_launch(void* const* d_in, const int* in_sizes, int n_in,
                              void* d_out, int out_size) {
    const float* hs      = (const float*)d_in[0];
    const float* Wq      = (const float*)d_in[1];
    const float* Wk      = (const float*)d_in[2];
    const float* Wv      = (const float*)d_in[3];
    const float* Wo      = (const float*)d_in[4];
    const float* Wg      = (const float*)d_in[5];
    const float* Win     = (const float*)d_in[6];
    const float* dt_bias = (const float*)d_in[7];
    const float* A_log   = (const float*)d_in[8];
    const float* gnorm   = (const float*)d_in[9];
    float* out = (float*)d_out;

    float *q, *k, *v, *gate, *y;
    cudaGetSymbolAddress((void**)&q, g_q);
    cudaGetSymbolAddress((void**)&k, g_k);
    cudaGetSymbolAddress((void**)&v, g_v);
    cudaGetSymbolAddress((void**)&gate, g_gate);
    cudaGetSymbolAddress((void**)&y, g_y);

    __nv_bfloat16 *hsh, *hsl, *wqh, *wql, *wgh, *wgl, *woh, *wol, *wkh, *wkl, *wvh, *wvl, *yh, *yl;
    cudaGetSymbolAddress((void**)&hsh, g_hsh); cudaGetSymbolAddress((void**)&hsl, g_hsl);
    cudaGetSymbolAddress((void**)&wqh, g_wqh); cudaGetSymbolAddress((void**)&wql, g_wql);
    cudaGetSymbolAddress((void**)&wgh, g_wgh); cudaGetSymbolAddress((void**)&wgl, g_wgl);
    cudaGetSymbolAddress((void**)&woh, g_woh); cudaGetSymbolAddress((void**)&wol, g_wol);
    cudaGetSymbolAddress((void**)&wkh, g_wkh); cudaGetSymbolAddress((void**)&wkl, g_wkl);
    cudaGetSymbolAddress((void**)&wvh, g_wvh); cudaGetSymbolAddress((void**)&wvl, g_wvl);
    cudaGetSymbolAddress((void**)&yh, g_yh);   cudaGetSymbolAddress((void**)&yl, g_yl);

    const int SMEM_BIG = (128 * 129 + 2 * 16 * 128) * (int)sizeof(float);
    cudaFuncSetAttribute(intra_kernel, cudaFuncAttributeMaxDynamicSharedMemorySize, SMEM_BIG);
    cudaFuncSetAttribute(inter_kernel, cudaFuncAttributeMaxDynamicSharedMemorySize, SMEM_BIG);
    const int SMEM_GEMM = 3 * 32768;  // 3 stages x 32KB
    cudaFuncSetAttribute(gemm_mma, cudaFuncAttributeMaxDynamicSharedMemorySize, SMEM_GEMM);

    // hi/lo conversions
    const int n4_big = (int)(NELEM_BIG / 4), n4_kv = (int)(NELEM_KV / 4);
    conv_split<<<(n4_big + 255) / 256, 256>>>(hs, hsh, hsl, n4_big);
    conv_split<<<(n4_big + 255) / 256, 256>>>(Wq, wqh, wql, n4_big);
    conv_split<<<(n4_big + 255) / 256, 256>>>(Wg, wgh, wgl, n4_big);
    conv_split<<<(n4_big + 255) / 256, 256>>>(Wo, woh, wol, n4_big);
    conv_split<<<(n4_kv + 255) / 256, 256>>>(Wk, wkh, wkl, n4_kv);
    conv_split<<<(n4_kv + 255) / 256, 256>>>(Wv, wvh, wvl, n4_kv);

    // projections (mma bf16x3, cp.async pipelined)
    gemm_mma<<<dim3(QDIM / 128, LSEQ / 128), 256, SMEM_GEMM>>>(hsh, hsl, wqh, wql, q, LSEQ, QDIM, HIDDEN);
    gemm_mma<<<dim3(KVDIM / 128, LSEQ / 128), 256, SMEM_GEMM>>>(hsh, hsl, wkh, wkl, k, LSEQ, KVDIM, HIDDEN);
    gemm_mma<<<dim3(KVDIM / 128, LSEQ / 128), 256, SMEM_GEMM>>>(hsh, hsl, wvh, wvl, v, LSEQ, KVDIM, HIDDEN);
    gemm_mma<<<dim3(QDIM / 128, LSEQ / 128), 256, SMEM_GEMM>>>(hsh, hsl, wgh, wgl, gate, LSEQ, QDIM, HIDDEN);
    dt_kernel<<<LSEQ, 256>>>(hs, Win, dt_bias);
    scan_kernel<<<NC * NH, 32>>>(A_log);

    // rope
    {
        long tq = (long)LSEQ * NH * 64;
        rope_kernel<<<(unsigned)((tq + 255) / 256), 256>>>(q, NH);
        long tk = (long)LSEQ * NKV * 64;
        rope_kernel<<<(unsigned)((tk + 255) / 256), 256>>>(k, NKV);
    }

    // attention
    intra_kernel<<<dim3(NC, NH), 256, SMEM_BIG>>>();
    recur_kernel<<<(NH * HD * HD + 1023) / 1024, 1024>>>();
    inter_kernel<<<dim3(NC, NH), 256, SMEM_BIG>>>(gnorm);

    // output projection
    conv_split<<<(n4_big + 255) / 256, 256>>>(y, yh, yl, n4_big);
    gemm_mma<<<dim3(HIDDEN / 128, LSEQ / 128), 256, SMEM_GEMM>>>(yh, yl, woh, wol, out, LSEQ, HIDDEN, QDIM);
}

// round 7
// speedup vs baseline: 1.2294x; 1.2294x over previous
#include <cuda_runtime.h>
#include <cuda_bf16.h>
#include <math.h>
#include <stdint.h>

#define LSEQ   4096
#define HIDDEN 4096
#define NH     32
#define NKV    8
#define HD     128
#define CHUNKS 128
#define NC     32
#define QDIM   4096   // NH*HD
#define KVDIM  1024   // NKV*HD
#define NELEM_BIG ((size_t)LSEQ * HIDDEN)     // 16M
#define NELEM_KV  ((size_t)KVDIM * HIDDEN)    // 4M

// single dynamic smem declaration for ALL kernels
extern __shared__ __align__(1024) unsigned char dyn_smem[];

// ---------------- scratch (static device globals; no allocation) ----------------
__device__ float g_q[(size_t)LSEQ * QDIM];
__device__ float g_k[(size_t)LSEQ * KVDIM];
__device__ float g_v[(size_t)LSEQ * KVDIM];
__device__ float g_gate[(size_t)LSEQ * QDIM];
__device__ float g_y[(size_t)LSEQ * QDIM];
__device__ float g_dt[LSEQ * NH];
__device__ float g_G[LSEQ * NH];
__device__ float g_cdec[NC * NH];
__device__ float g_cs[(size_t)NC * NH * HD * HD];
__device__ float g_prev[(size_t)NC * NH * HD * HD];

// bf16 hi/lo split buffers
__device__ __nv_bfloat16 g_hsh[NELEM_BIG], g_hsl[NELEM_BIG];
__device__ __nv_bfloat16 g_wqh[NELEM_BIG], g_wql[NELEM_BIG];
__device__ __nv_bfloat16 g_wgh[NELEM_BIG], g_wgl[NELEM_BIG];
__device__ __nv_bfloat16 g_woh[NELEM_BIG], g_wol[NELEM_BIG];
__device__ __nv_bfloat16 g_wkh[NELEM_KV],  g_wkl[NELEM_KV];
__device__ __nv_bfloat16 g_wvh[NELEM_KV],  g_wvl[NELEM_KV];
__device__ __nv_bfloat16 g_yh[NELEM_BIG],  g_yl[NELEM_BIG];

// ---------------- fp32 -> bf16 hi/lo split ----------------
__global__ void conv_split(const float* __restrict__ src, __nv_bfloat16* __restrict__ hi,
                           __nv_bfloat16* __restrict__ lo, int n4) {
    int i = blockIdx.x * blockDim.x + threadIdx.x;
    if (i >= n4) return;
    float4 v = ((const float4*)src)[i];
    __nv_bfloat162 h01 = __floats2bfloat162_rn(v.x, v.y);
    __nv_bfloat162 h23 = __floats2bfloat162_rn(v.z, v.w);
    float2 f01 = __bfloat1622float2(h01);
    float2 f23 = __bfloat1622float2(h23);
    __nv_bfloat162 l01 = __floats2bfloat162_rn(v.x - f01.x, v.y - f01.y);
    __nv_bfloat162 l23 = __floats2bfloat162_rn(v.z - f23.x, v.w - f23.y);
    ((__nv_bfloat162*)hi)[2 * i]     = h01;
    ((__nv_bfloat162*)hi)[2 * i + 1] = h23;
    ((__nv_bfloat162*)lo)[2 * i]     = l01;
    ((__nv_bfloat162*)lo)[2 * i + 1] = l23;
}

// ---------------- bf16x3 tensor-core GEMM (pre-split inputs) ----------------
// C[M,N] = (Ah+Al)[M,K] @ (Bh+Bl)[N,K]^T, fp32 acc, MMAs: hh + hl + lh.
// 128x128 CTA tile, BK=32, 256 threads (8 warps 2x4), warp tile 64x32, m16n8k16.
// smem fragment-permuted (identical layout to the round-3 58.8%-tensor kernel):
// per buffer (8192 u32): Ah@0, Al@2048, Bh@4096, Bl@6144; 2 buffers (64KB).
__global__ void __launch_bounds__(256, 1) gemm_mma3(const __nv_bfloat16* __restrict__ Ah,
                                                    const __nv_bfloat16* __restrict__ Al,
                                                    const __nv_bfloat16* __restrict__ Bh,
                                                    const __nv_bfloat16* __restrict__ Bl,
                                                    float* __restrict__ C,
                                                    int M, int N, int K) {
    unsigned* smem_u = (unsigned*)dyn_smem;
    const int tid = threadIdx.x;
    const int warp = tid >> 5, lane = tid & 31;
    const int wm = warp >> 2, wn = warp & 3;   // 2 x 4 warp grid
    const int bm = blockIdx.y * 128, bn = blockIdx.x * 128;

    float acc[4][4][4];
#pragma unroll
    for (int a = 0; a < 4; a++)
#pragma unroll
        for (int b = 0; b < 4; b++)
#pragma unroll
            for (int c = 0; c < 4; c++) acc[a][b][c] = 0.f;

    // staging address precompute: per i, this thread covers row, k0..k0+3 (2 u32 words)
    const __nv_bfloat16* ag_h[4];
    const __nv_bfloat16* ag_l[4];
    const __nv_bfloat16* bg_h[4];
    const __nv_bfloat16* bg_l[4];
    int a_st[4], b_st[4];
#pragma unroll
    for (int i = 0; i < 4; i++) {
        const int idx = tid + i * 256;
        const int row = idx >> 3, c4 = idx & 7;
        const int k0 = c4 * 4;
        const int ks = k0 >> 4, ki = k0 & 15;
        ag_h[i] = Ah + (size_t)(bm + row) * K + k0;
        ag_l[i] = Al + (size_t)(bm + row) * K + k0;
        bg_h[i] = Bh + (size_t)(bn + row) * K + k0;
        bg_l[i] = Bl + (size_t)(bn + row) * K + k0;
        const int ri = row & 15, tm = row >> 4;
        const int laneA = (ri & 7) * 4 + ((ki & 7) >> 1);
        const int regA = (ri >> 3) + ((ki >> 3) << 1);
        a_st[i] = ((ks * 8 + tm) * 32 + laneA) * 4 + regA;
        const int ci = row & 7, tn = row >> 3;
        const int laneB = ci * 4 + ((ki & 7) >> 1);
        const int regB = ki >> 3;
        b_st[i] = ((ks * 16 + tn) * 32 + laneB) * 2 + regB;
    }

    uint2 arh[4], arl[4], brh[4], brl[4];
#pragma unroll
    for (int i = 0; i < 4; i++) {
        arh[i] = *(const uint2*)(ag_h[i]);
        arl[i] = *(const uint2*)(ag_l[i]);
        brh[i] = *(const uint2*)(bg_h[i]);
        brl[i] = *(const uint2*)(bg_l[i]);
    }

    auto store_tiles = [&](unsigned* base) {
        unsigned* Ahs = base;
        unsigned* Als = base + 2048;
        unsigned* Bhs = base + 4096;
        unsigned* Bls = base + 6144;
#pragma unroll
        for (int i = 0; i < 4; i++) {
            Ahs[a_st[i]]     = arh[i].x;
            Ahs[a_st[i] + 4] = arh[i].y;
            Als[a_st[i]]     = arl[i].x;
            Als[a_st[i] + 4] = arl[i].y;
            Bhs[b_st[i]]     = brh[i].x;
            Bhs[b_st[i] + 2] = brh[i].y;
            Bls[b_st[i]]     = brl[i].x;
            Bls[b_st[i] + 2] = brl[i].y;
        }
    };

    store_tiles(smem_u);
    __syncthreads();

    const int nk = K >> 5;
    for (int kb = 0; kb < nk; kb++) {
        const int cur = kb & 1;
        const bool has_next = (kb + 1) < nk;
        if (has_next) {
            const int off = (kb + 1) * 32;
#pragma unroll
            for (int i = 0; i < 4; i++) {
                arh[i] = *(const uint2*)(ag_h[i] + off);
                arl[i] = *(const uint2*)(ag_l[i] + off);
                brh[i] = *(const uint2*)(bg_h[i] + off);
                brl[i] = *(const uint2*)(bg_l[i] + off);
            }
        }
        const unsigned* base = smem_u + cur * 8192;
        const unsigned* Ahb = base;
        const unsigned* Alb = base + 2048;
        const unsigned* Bhb = base + 4096;
        const unsigned* Blb = base + 6144;
#pragma unroll
        for (int ks = 0; ks < 2; ks++) {
            unsigned bh[4][2], bl[4][2];
#pragma unroll
            for (int nt = 0; nt < 4; nt++) {
                const int tn = wn * 4 + nt;
                uint2 vh = *(const uint2*)(Bhb + ((ks * 16 + tn) * 32 + lane) * 2);
                uint2 vl = *(const uint2*)(Blb + ((ks * 16 + tn) * 32 + lane) * 2);
                bh[nt][0] = vh.x; bh[nt][1] = vh.y;
                bl[nt][0] = vl.x; bl[nt][1] = vl.y;
            }
#pragma unroll
            for (int mt = 0; mt < 4; mt++) {
                const int tm = wm * 4 + mt;
                uint4 avh = *(const uint4*)(Ahb + ((ks * 8 + tm) * 32 + lane) * 4);
                uint4 avl = *(const uint4*)(Alb + ((ks * 8 + tm) * 32 + lane) * 4);
#pragma unroll
                for (int nt = 0; nt < 4; nt++) {
                    asm volatile(
                        "mma.sync.aligned.m16n8k16.row.col.f32.bf16.bf16.f32 "
                        "{%0,%1,%2,%3}, {%4,%5,%6,%7}, {%8,%9}, {%0,%1,%2,%3};"
                        : "+f"(acc[mt][nt][0]), "+f"(acc[mt][nt][1]),
                          "+f"(acc[mt][nt][2]), "+f"(acc[mt][nt][3])
                        : "r"(avh.x), "r"(avh.y), "r"(avh.z), "r"(avh.w),
                          "r"(bh[nt][0]), "r"(bh[nt][1]));
                    asm volatile(
                        "mma.sync.aligned.m16n8k16.row.col.f32.bf16.bf16.f32 "
                        "{%0,%1,%2,%3}, {%4,%5,%6,%7}, {%8,%9}, {%0,%1,%2,%3};"
                        : "+f"(acc[mt][nt][0]), "+f"(acc[mt][nt][1]),
                          "+f"(acc[mt][nt][2]), "+f"(acc[mt][nt][3])
                        : "r"(avh.x), "r"(avh.y), "r"(avh.z), "r"(avh.w),
                          "r"(bl[nt][0]), "r"(bl[nt][1]));
                    asm volatile(
                        "mma.sync.aligned.m16n8k16.row.col.f32.bf16.bf16.f32 "
                        "{%0,%1,%2,%3}, {%4,%5,%6,%7}, {%8,%9}, {%0,%1,%2,%3};"
                        : "+f"(acc[mt][nt][0]), "+f"(acc[mt][nt][1]),
                          "+f"(acc[mt][nt][2]), "+f"(acc[mt][nt][3])
                        : "r"(avl.x), "r"(avl.y), "r"(avl.z), "r"(avl.w),
                          "r"(bh[nt][0]), "r"(bh[nt][1]));
                }
            }
        }
        if (has_next) {
            store_tiles(smem_u + ((kb + 1) & 1) * 8192);
            __syncthreads();
        }
    }

    // epilogue
#pragma unroll
    for (int mt = 0; mt < 4; mt++) {
        const int row0 = bm + wm * 64 + mt * 16 + (lane >> 2);
#pragma unroll
        for (int nt = 0; nt < 4; nt++) {
            const int col = bn + wn * 32 + nt * 8 + (lane & 3) * 2;
            *(float2*)(C + (size_t)row0 * N + col) = make_float2(acc[mt][nt][0], acc[mt][nt][1]);
            *(float2*)(C + (size_t)(row0 + 8) * N + col) = make_float2(acc[mt][nt][2], acc[mt][nt][3]);
        }
    }
}

// ---------------- dt = softplus(hs @ Win^T + dt_bias) ----------------
__global__ void dt_kernel(const float* __restrict__ hs, const float* __restrict__ Win,
                          const float* __restrict__ dtb) {
    __shared__ float srow[HIDDEN];
    __shared__ float red[256];
    const int l = blockIdx.x;
    for (int k = threadIdx.x; k < HIDDEN; k += 256) srow[k] = hs[(size_t)l * HIDDEN + k];
    __syncthreads();
    const int h = threadIdx.x & 31;
    const int part = threadIdx.x >> 5;
    const float* w = Win + (size_t)h * HIDDEN + part * 512;
    const float* s = srow + part * 512;
    float acc = 0.f;
#pragma unroll 4
    for (int k = 0; k < 512; k++) acc += s[k] * w[k];
    red[threadIdx.x] = acc;
    __syncthreads();
    if (threadIdx.x < 32) {
        float t = 0.f;
#pragma unroll
        for (int p = 0; p < 8; p++) t += red[p * 32 + h];
        t += dtb[h];
        float sp = fmaxf(t, 0.f) + log1pf(expf(-fabsf(t)));
        g_dt[l * NH + h] = sp;
    }
}

// ---------------- per-(chunk,head) inclusive cumsum of g = dt*A ----------------
__global__ void scan_kernel(const float* __restrict__ A_log) {
    const int hc = blockIdx.x;
    const int h = hc & (NH - 1);
    const int c = hc >> 5;
    const float A = -expf(A_log[h]);
    const int lane = threadIdx.x;
    float carry = 0.f;
    for (int s0 = 0; s0 < CHUNKS; s0 += 32) {
        const int l = c * CHUNKS + s0 + lane;
        float val = g_dt[l * NH + h] * A;
#pragma unroll
        for (int off = 1; off < 32; off <<= 1) {
            float n = __shfl_up_sync(0xffffffffu, val, off);
            if (lane >= off) val += n;
        }
        val += carry;
        g_G[l * NH + h] = val;
        carry = __shfl_sync(0xffffffffu, val, 31);
    }
    if (lane == 31) g_cdec[c * NH + h] = expf(carry);
}

// ---------------- RoPE in place ----------------
__global__ void rope_kernel(float* __restrict__ x, int nheads) {
    const long idx = (long)blockIdx.x * blockDim.x + threadIdx.x;
    const long total = (long)LSEQ * nheads * 64;
    if (idx >= total) return;
    const int d = (int)(idx & 63);
    const int h = (int)((idx >> 6) % nheads);
    const long l = idx / ((long)64 * nheads);
    const float inv = powf(10000.0f, -(2.0f * d) / 128.0f);
    const float ang = (float)l * inv;
    float cs, sn;
    __sincosf(ang, &sn, &cs);
    float* base = x + l * (size_t)(nheads * HD) + (size_t)h * HD;
    const float x1 = base[d];
    const float x2 = base[d + 64];
    base[d]      = x1 * cs - x2 * sn;
    base[d + 64] = x2 * cs + x1 * sn;
}

// ---------------- intra-chunk: scores, decay mask, y_intra, cstates ----------------
__global__ void intra_kernel() {
    float* smem = (float*)dyn_smem;
    float* sP = smem;                 // 128*129, P^T (stored [j][i])
    float* sA = sP + 128 * 129;       // 16*128
    float* sB = sA + 16 * 128;        // 16*128
    __shared__ float sG[128];
    __shared__ float sDt[128];

    const int c = blockIdx.x, h = blockIdx.y;
    const int kvh = h >> 2;
    const int tid = threadIdx.x;
    const int tr = tid >> 4, tc = tid & 15;
    const float* qp = g_q + (size_t)(c * CHUNKS) * QDIM + (size_t)h * HD;
    const float* kp = g_k + (size_t)(c * CHUNKS) * KVDIM + (size_t)kvh * HD;
    const float* vp = g_v + (size_t)(c * CHUNKS) * KVDIM + (size_t)kvh * HD;

    if (tid < 128) {
        sG[tid] = g_G[(c * CHUNKS + tid) * NH + h];
        sDt[tid] = g_dt[(c * CHUNKS + tid) * NH + h];
    }
    __syncthreads();
    const float Glast = sG[127];

    float acc[8][8];
#pragma unroll
    for (int i = 0; i < 8; i++)
#pragma unroll
        for (int j = 0; j < 8; j++) acc[i][j] = 0.f;

    const int rowA = tid >> 1;
    const int kk0 = (tid & 1) * 8;
    for (int d0 = 0; d0 < HD; d0 += 16) {
        const float* ap = qp + (size_t)rowA * QDIM + d0 + kk0;
        float4 a0 = *(const float4*)ap;
        float4 a1 = *(const float4*)(ap + 4);
        sA[(kk0 + 0) * 128 + rowA] = a0.x;
        sA[(kk0 + 1) * 128 + rowA] = a0.y;
        sA[(kk0 + 2) * 128 + rowA] = a0.z;
        sA[(kk0 + 3) * 128 + rowA] = a0.w;
        sA[(kk0 + 4) * 128 + rowA] = a1.x;
        sA[(kk0 + 5) * 128 + rowA] = a1.y;
        sA[(kk0 + 6) * 128 + rowA] = a1.z;
        sA[(kk0 + 7) * 128 + rowA] = a1.w;
        const float* bp = kp + (size_t)rowA * KVDIM + d0 + kk0;
        float4 b0 = *(const float4*)bp;
        float4 b1 = *(const float4*)(bp + 4);
        sB[(kk0 + 0) * 128 + rowA] = b0.x;
        sB[(kk0 + 1) * 128 + rowA] = b0.y;
        sB[(kk0 + 2) * 128 + rowA] = b0.z;
        sB[(kk0 + 3) * 128 + rowA] = b0.w;
        sB[(kk0 + 4) * 128 + rowA] = b1.x;
        sB[(kk0 + 5) * 128 + rowA] = b1.y;
        sB[(kk0 + 6) * 128 + rowA] = b1.z;
        sB[(kk0 + 7) * 128 + rowA] = b1.w;
        __syncthreads();
#pragma unroll
        for (int kk = 0; kk < 16; kk++) {
            float av[8], bv[8];
#pragma unroll
            for (int i = 0; i < 8; i++) av[i] = sA[kk * 128 + tr * 8 + i];
#pragma unroll
            for (int j = 0; j < 8; j++) bv[j] = sB[kk * 128 + tc * 8 + j];
#pragma unroll
            for (int i = 0; i < 8; i++)
#pragma unroll
                for (int j = 0; j < 8; j++) acc[i][j] += av[i] * bv[j];
        }
        __syncthreads();
    }

#pragma unroll
    for (int ii = 0; ii < 8; ii++) {
        const int i = tr * 8 + ii;
        const float Gi = sG[i];
#pragma unroll
        for (int jj = 0; jj < 8; jj++) {
            const int j = tc * 8 + jj;
            const float p = (i >= j) ? acc[ii][jj] * expf(Gi - sG[j]) : 0.f;
            sP[j * 129 + i] = p;
        }
    }
    __syncthreads();

#pragma unroll
    for (int i = 0; i < 8; i++)
#pragma unroll
        for (int j = 0; j < 8; j++) acc[i][j] = 0.f;
    {
        const int kkl = tid >> 4;
        const int e0 = (tid & 15) * 8;
        for (int j0 = 0; j0 < 128; j0 += 16) {
            const float dtv = sDt[j0 + kkl];
            const float* xp = vp + (size_t)(j0 + kkl) * KVDIM + e0;
            float4 x0 = *(const float4*)xp;
            float4 x1 = *(const float4*)(xp + 4);
            sB[kkl * 128 + e0 + 0] = x0.x * dtv;
            sB[kkl * 128 + e0 + 1] = x0.y * dtv;
            sB[kkl * 128 + e0 + 2] = x0.z * dtv;
            sB[kkl * 128 + e0 + 3] = x0.w * dtv;
            sB[kkl * 128 + e0 + 4] = x1.x * dtv;
            sB[kkl * 128 + e0 + 5] = x1.y * dtv;
            sB[kkl * 128 + e0 + 6] = x1.z * dtv;
            sB[kkl * 128 + e0 + 7] = x1.w * dtv;
            __syncthreads();
#pragma unroll
            for (int kk = 0; kk < 16; kk++) {
                float av[8], bv[8];
#pragma unroll
                for (int i = 0; i < 8; i++) av[i] = sP[(j0 + kk) * 129 + tr * 8 + i];
#pragma unroll
                for (int j = 0; j < 8; j++) bv[j] = sB[kk * 128 + tc * 8 + j];
#pragma unroll
                for (int i = 0; i < 8; i++)
#pragma unroll
                    for (int j = 0; j < 8; j++) acc[i][j] += av[i] * bv[j];
            }
            __syncthreads();
        }
    }
#pragma unroll
    for (int ii = 0; ii < 8; ii++) {
        float* yp = g_y + (size_t)(c * CHUNKS + tr * 8 + ii) * QDIM + (size_t)h * HD + tc * 8;
        *(float4*)yp = make_float4(acc[ii][0], acc[ii][1], acc[ii][2], acc[ii][3]);
        *(float4*)(yp + 4) = make_float4(acc[ii][4], acc[ii][5], acc[ii][6], acc[ii][7]);
    }

#pragma unroll
    for (int i = 0; i < 8; i++)
#pragma unroll
        for (int j = 0; j < 8; j++) acc[i][j] = 0.f;
    {
        const int kkl = tid >> 4;
        const int e0 = (tid & 15) * 8;
        for (int j0 = 0; j0 < 128; j0 += 16) {
            const float w = expf(Glast - sG[j0 + kkl]);
            const float dtv = sDt[j0 + kkl];
            const float* kp2 = kp + (size_t)(j0 + kkl) * KVDIM + e0;
            const float* xp = vp + (size_t)(j0 + kkl) * KVDIM + e0;
            float4 k0v = *(const float4*)kp2;
            float4 k1v = *(const float4*)(kp2 + 4);
            float4 x0 = *(const float4*)xp;
            float4 x1 = *(const float4*)(xp + 4);
            sA[kkl * 128 + e0 + 0] = k0v.x * w;
            sA[kkl * 128 + e0 + 1] = k0v.y * w;
            sA[kkl * 128 + e0 + 2] = k0v.z * w;
            sA[kkl * 128 + e0 + 3] = k0v.w * w;
            sA[kkl * 128 + e0 + 4] = k1v.x * w;
            sA[kkl * 128 + e0 + 5] = k1v.y * w;
            sA[kkl * 128 + e0 + 6] = k1v.z * w;
            sA[kkl * 128 + e0 + 7] = k1v.w * w;
            sB[kkl * 128 + e0 + 0] = x0.x * dtv;
            sB[kkl * 128 + e0 + 1] = x0.y * dtv;
            sB[kkl * 128 + e0 + 2] = x0.z * dtv;
            sB[kkl * 128 + e0 + 3] = x0.w * dtv;
            sB[kkl * 128 + e0 + 4] = x1.x * dtv;
            sB[kkl * 128 + e0 + 5] = x1.y * dtv;
            sB[kkl * 128 + e0 + 6] = x1.z * dtv;
            sB[kkl * 128 + e0 + 7] = x1.w * dtv;
            __syncthreads();
#pragma unroll
            for (int kk = 0; kk < 16; kk++) {
                float av[8], bv[8];
#pragma unroll
                for (int i = 0; i < 8; i++) av[i] = sA[kk * 128 + tr * 8 + i];
#pragma unroll
                for (int j = 0; j < 8; j++) bv[j] = sB[kk * 128 + tc * 8 + j];
#pragma unroll
                for (int i = 0; i < 8; i++)
#pragma unroll
                    for (int j = 0; j < 8; j++) acc[i][j] += av[i] * bv[j];
            }
            __syncthreads();
        }
    }
    float* csp = g_cs + (size_t)(c * NH + h) * HD * HD;
#pragma unroll
    for (int ii = 0; ii < 8; ii++) {
        float* cp = csp + (size_t)(tr * 8 + ii) * HD + tc * 8;
        *(float4*)cp = make_float4(acc[ii][0], acc[ii][1], acc[ii][2], acc[ii][3]);
        *(float4*)(cp + 4) = make_float4(acc[ii][4], acc[ii][5], acc[ii][6], acc[ii][7]);
    }
}

// ---------------- sequential chunk recurrence ----------------
__global__ void recur_kernel() {
    const int idx = blockIdx.x * blockDim.x + threadIdx.x;
    if (idx >= NH * HD * HD) return;
    const int h = idx / (HD * HD);
    const int de = idx % (HD * HD);
    float state = 0.f;
#pragma unroll 1
    for (int c = 0; c < NC; c++) {
        const size_t off = (size_t)(c * NH + h) * HD * HD + de;
        g_prev[off] = state;
        state = state * g_cdec[c * NH + h] + g_cs[off];
    }
}

// ---------------- inter-chunk + combine + RMSNorm + SiLU gate -> bf16 hi/lo y ----------------
__global__ void inter_kernel(const float* __restrict__ gnorm) {
    float* smem = (float*)dyn_smem;
    float* sY = smem;               // 128*129
    float* sA = sY + 128 * 129;     // 16*128
    float* sB = sA + 16 * 128;      // 16*128
    __shared__ float sG[128];
    __shared__ float sScale[128];
    __shared__ float sGn[128];

    const int c = blockIdx.x, h = blockIdx.y;
    const int tid = threadIdx.x;
    const int tr = tid >> 4, tc = tid & 15;
    const float* qp = g_q + (size_t)(c * CHUNKS) * QDIM + (size_t)h * HD;
    const float* pp = g_prev + (size_t)(c * NH + h) * HD * HD;

    if (tid < 128) {
        sG[tid] = g_G[(c * CHUNKS + tid) * NH + h];
        sGn[tid] = gnorm[tid];
    }
    __syncthreads();

    float acc[8][8];
#pragma unroll
    for (int i = 0; i < 8; i++)
#pragma unroll
        for (int j = 0; j < 8; j++) acc[i][j] = 0.f;

    const int rowA = tid >> 1;
    const int kk0 = (tid & 1) * 8;
    const int kkl = tid >> 4;
    const int e0 = (tid & 15) * 8;
    for (int d0 = 0; d0 < HD; d0 += 16) {
        const float eg = expf(sG[rowA]);
        const float* ap = qp + (size_t)rowA * QDIM + d0 + kk0;
        float4 a0 = *(const float4*)ap;
        float4 a1 = *(const float4*)(ap + 4);
        sA[(kk0 + 0) * 128 + rowA] = a0.x * eg;
        sA[(kk0 + 1) * 128 + rowA] = a0.y * eg;
        sA[(kk0 + 2) * 128 + rowA] = a0.z * eg;
        sA[(kk0 + 3) * 128 + rowA] = a0.w * eg;
        sA[(kk0 + 4) * 128 + rowA] = a1.x * eg;
        sA[(kk0 + 5) * 128 + rowA] = a1.y * eg;
        sA[(kk0 + 6) * 128 + rowA] = a1.z * eg;
        sA[(kk0 + 7) * 128 + rowA] = a1.w * eg;
        const float* bp = pp + (size_t)(d0 + kkl) * HD + e0;
        float4 b0 = *(const float4*)bp;
        float4 b1 = *(const float4*)(bp + 4);
        sB[kkl * 128 + e0 + 0] = b0.x;
        sB[kkl * 128 + e0 + 1] = b0.y;
        sB[kkl * 128 + e0 + 2] = b0.z;
        sB[kkl * 128 + e0 + 3] = b0.w;
        sB[kkl * 128 + e0 + 4] = b1.x;
        sB[kkl * 128 + e0 + 5] = b1.y;
        sB[kkl * 128 + e0 + 6] = b1.z;
        sB[kkl * 128 + e0 + 7] = b1.w;
        __syncthreads();
#pragma unroll
        for (int kk = 0; kk < 16; kk++) {
            float av[8], bv[8];
#pragma unroll
            for (int i = 0; i < 8; i++) av[i] = sA[kk * 128 + tr * 8 + i];
#pragma unroll
            for (int j = 0; j < 8; j++) bv[j] = sB[kk * 128 + tc * 8 + j];
#pragma unroll
            for (int i = 0; i < 8; i++)
#pragma unroll
                for (int j = 0; j < 8; j++) acc[i][j] += av[i] * bv[j];
        }
        __syncthreads();
    }

#pragma unroll
    for (int ii = 0; ii < 8; ii++) {
        const int i = tr * 8 + ii;
        const float* yin = g_y + (size_t)(c * CHUNKS + i) * QDIM + (size_t)h * HD + tc * 8;
#pragma unroll
        for (int jj = 0; jj < 8; jj++) {
            sY[i * 129 + tc * 8 + jj] = acc[ii][jj] + yin[jj];
        }
    }
    __syncthreads();

    if (tid < 128) {
        float s = 0.f;
#pragma unroll 4
        for (int e = 0; e < 128; e++) {
            float t = sY[tid * 129 + e];
            s += t * t;
        }
        sScale[tid] = rsqrtf(s * (1.0f / 128.0f) + 1e-5f);
    }
    __syncthreads();

    // gate + write bf16 hi/lo split directly (consumed by output GEMM)
    for (int idx = tid; idx < 128 * 128; idx += 256) {
        const int i = idx >> 7, e = idx & 127;
        const size_t off = (size_t)(c * CHUNKS + i) * QDIM + (size_t)h * HD + e;
        const float gv = g_gate[off];
        const float sig = 1.f / (1.f + expf(-gv));
        const float val = sY[i * 129 + e] * sScale[i] * sGn[e] * gv * sig;
        const __nv_bfloat16 hv = __float2bfloat16(val);
        g_yh[off] = hv;
        g_yl[off] = __float2bfloat16(val - __bfloat162float(hv));
    }
}

// ---------------- launch ----------------
extern "C" void kernel_launch(void* const* d_in, const int* in_sizes, int n_in,
                              void* d_out, int out_size) {
    const float* hs      = (const float*)d_in[0];
    const float* Wq      = (const float*)d_in[1];
    const float* Wk      = (const float*)d_in[2];
    const float* Wv      = (const float*)d_in[3];
    const float* Wo      = (const float*)d_in[4];
    const float* Wg      = (const float*)d_in[5];
    const float* Win     = (const float*)d_in[6];
    const float* dt_bias = (const float*)d_in[7];
    const float* A_log   = (const float*)d_in[8];
    const float* gnorm   = (const float*)d_in[9];
    float* out = (float*)d_out;

    float *q, *k, *v, *gate, *y;
    cudaGetSymbolAddress((void**)&q, g_q);
    cudaGetSymbolAddress((void**)&k, g_k);
    cudaGetSymbolAddress((void**)&v, g_v);
    cudaGetSymbolAddress((void**)&gate, g_gate);
    cudaGetSymbolAddress((void**)&y, g_y);

    __nv_bfloat16 *hsh, *hsl, *wqh, *wql, *wgh, *wgl, *woh, *wol, *wkh, *wkl, *wvh, *wvl, *yh, *yl;
    cudaGetSymbolAddress((void**)&hsh, g_hsh); cudaGetSymbolAddress((void**)&hsl, g_hsl);
    cudaGetSymbolAddress((void**)&wqh, g_wqh); cudaGetSymbolAddress((void**)&wql, g_wql);
    cudaGetSymbolAddress((void**)&wgh, g_wgh); cudaGetSymbolAddress((void**)&wgl, g_wgl);
    cudaGetSymbolAddress((void**)&woh, g_woh); cudaGetSymbolAddress((void**)&wol, g_wol);
    cudaGetSymbolAddress((void**)&wkh, g_wkh); cudaGetSymbolAddress((void**)&wkl, g_wkl);
    cudaGetSymbolAddress((void**)&wvh, g_wvh); cudaGetSymbolAddress((void**)&wvl, g_wvl);
    cudaGetSymbolAddress((void**)&yh, g_yh);   cudaGetSymbolAddress((void**)&yl, g_yl);

    const int SMEM_BIG = (128 * 129 + 2 * 16 * 128) * (int)sizeof(float);
    cudaFuncSetAttribute(intra_kernel, cudaFuncAttributeMaxDynamicSharedMemorySize, SMEM_BIG);
    cudaFuncSetAttribute(inter_kernel, cudaFuncAttributeMaxDynamicSharedMemorySize, SMEM_BIG);
    const int SMEM_GEMM = 16384 * (int)sizeof(unsigned);  // 64KB (2 x 32KB buffers)
    cudaFuncSetAttribute(gemm_mma3, cudaFuncAttributeMaxDynamicSharedMemorySize, SMEM_GEMM);

    // hi/lo conversions (inputs only; y split is fused into inter_kernel)
    const int n4_big = (int)(NELEM_BIG / 4), n4_kv = (int)(NELEM_KV / 4);
    conv_split<<<(n4_big + 255) / 256, 256>>>(hs, hsh, hsl, n4_big);
    conv_split<<<(n4_big + 255) / 256, 256>>>(Wq, wqh, wql, n4_big);
    conv_split<<<(n4_big + 255) / 256, 256>>>(Wg, wgh, wgl, n4_big);
    conv_split<<<(n4_big + 255) / 256, 256>>>(Wo, woh, wol, n4_big);
    conv_split<<<(n4_kv + 255) / 256, 256>>>(Wk, wkh, wkl, n4_kv);
    conv_split<<<(n4_kv + 255) / 256, 256>>>(Wv, wvh, wvl, n4_kv);

    // projections (tensor core, bf16x3 compensated, pre-split inputs)
    gemm_mma3<<<dim3(QDIM / 128, LSEQ / 128), 256, SMEM_GEMM>>>(hsh, hsl, wqh, wql, q, LSEQ, QDIM, HIDDEN);
    gemm_mma3<<<dim3(KVDIM / 128, LSEQ / 128), 256, SMEM_GEMM>>>(hsh, hsl, wkh, wkl, k, LSEQ, KVDIM, HIDDEN);
    gemm_mma3<<<dim3(KVDIM / 128, LSEQ / 128), 256, SMEM_GEMM>>>(hsh, hsl, wvh, wvl, v, LSEQ, KVDIM, HIDDEN);
    gemm_mma3<<<dim3(QDIM / 128, LSEQ / 128), 256, SMEM_GEMM>>>(hsh, hsl, wgh, wgl, gate, LSEQ, QDIM, HIDDEN);
    dt_kernel<<<LSEQ, 256>>>(hs, Win, dt_bias);
    scan_kernel<<<NC * NH, 32>>>(A_log);

    // rope
    {
        long tq = (long)LSEQ * NH * 64;
        rope_kernel<<<(unsigned)((tq + 255) / 256), 256>>>(q, NH);
        long tk = (long)LSEQ * NKV * 64;
        rope_kernel<<<(unsigned)((tk + 255) / 256), 256>>>(k, NKV);
    }

    // attention
    intra_kernel<<<dim3(NC, NH), 256, SMEM_BIG>>>();
    recur_kernel<<<(NH * HD * HD + 1023) / 1024, 1024>>>();
    inter_kernel<<<dim3(NC, NH), 256, SMEM_BIG>>>(gnorm);

    // output projection (y already split by inter_kernel)
    gemm_mma3<<<dim3(HIDDEN / 128, LSEQ / 128), 256, SMEM_GEMM>>>(yh, yl, woh, wol, out, LSEQ, HIDDEN, QDIM);
}